// round 1
// baseline (speedup 1.0000x reference)
#include <cuda_runtime.h>

// IFOPooling: h_t = f_t * h_{t-1} + i_t * z_t over seq dim (innermost, S=2048)
// for B*H = 16384 independent rows. Pure HBM-bound: 512MB traffic.
//
// Strategy: one warp per row. Each lane owns a contiguous 16-element chunk
// (4x float4 loads). Per tile of 512 elements:
//   1) lane computes affine map of its chunk: h_out = A*h_in + b
//   2) warp-wide inclusive scan composing affine maps via shfl_up (5 steps)
//   3) lane recomputes its 16 outputs from its incoming carry (regs only)
// Scalar carry h chains the 4 tiles.

#define SEQ 2048
#define PER_LANE 16
#define TILE (32 * PER_LANE)       // 512
#define NTILES (SEQ / TILE)        // 4

__global__ void __launch_bounds__(256) ifo_scan_kernel(
    const float4* __restrict__ f4,
    const float4* __restrict__ z4,
    const float4* __restrict__ i4,
    float4* __restrict__ o4,
    int rows)
{
    const int gwarp = (blockIdx.x * blockDim.x + threadIdx.x) >> 5;
    const int lane  = threadIdx.x & 31;
    if (gwarp >= rows) return;

    const int row_base4 = gwarp * (SEQ / 4);   // row offset in float4 units

    float h = 0.0f;  // carry across tiles

    #pragma unroll
    for (int t = 0; t < NTILES; ++t) {
        const int base4 = row_base4 + t * (TILE / 4) + lane * (PER_LANE / 4);

        // ---- load chunk: f and x = i*z (registers) ----
        float4 fv[4], xv[4];
        #pragma unroll
        for (int j = 0; j < 4; ++j) {
            float4 ff = f4[base4 + j];
            float4 zz = z4[base4 + j];
            float4 ii = i4[base4 + j];
            fv[j] = ff;
            xv[j] = make_float4(ii.x * zz.x, ii.y * zz.y,
                                ii.z * zz.z, ii.w * zz.w);
        }

        // ---- local affine map of the chunk: h_out = A*h_in + b ----
        float A = 1.0f, b = 0.0f;
        #pragma unroll
        for (int j = 0; j < 4; ++j) {
            b = fmaf(fv[j].x, b, xv[j].x);  A *= fv[j].x;
            b = fmaf(fv[j].y, b, xv[j].y);  A *= fv[j].y;
            b = fmaf(fv[j].z, b, xv[j].z);  A *= fv[j].z;
            b = fmaf(fv[j].w, b, xv[j].w);  A *= fv[j].w;
        }

        // ---- warp inclusive scan composing affine maps ----
        // (A,b) <- (A,b) o (Ap,bp) : A = A*Ap, b = A*bp + b
        #pragma unroll
        for (int d = 1; d < 32; d <<= 1) {
            float Ap = __shfl_up_sync(0xffffffffu, A, d);
            float bp = __shfl_up_sync(0xffffffffu, b, d);
            if (lane >= d) {
                b = fmaf(A, bp, b);
                A *= Ap;
            }
        }

        // incoming carry for this lane = exclusive prefix applied to tile carry
        float Aex = __shfl_up_sync(0xffffffffu, A, 1);
        float bex = __shfl_up_sync(0xffffffffu, b, 1);
        float h_in = (lane == 0) ? h : fmaf(Aex, h, bex);

        // tile carry-out from lane 31's inclusive map
        float A31 = __shfl_sync(0xffffffffu, A, 31);
        float b31 = __shfl_sync(0xffffffffu, b, 31);

        // ---- second pass: emit outputs ----
        float hh = h_in;
        #pragma unroll
        for (int j = 0; j < 4; ++j) {
            float4 ov;
            hh = fmaf(fv[j].x, hh, xv[j].x); ov.x = hh;
            hh = fmaf(fv[j].y, hh, xv[j].y); ov.y = hh;
            hh = fmaf(fv[j].z, hh, xv[j].z); ov.z = hh;
            hh = fmaf(fv[j].w, hh, xv[j].w); ov.w = hh;
            o4[base4 + j] = ov;
        }

        h = fmaf(A31, h, b31);
    }
}

extern "C" void kernel_launch(void* const* d_in, const int* in_sizes, int n_in,
                              void* d_out, int out_size)
{
    const float4* f = (const float4*)d_in[0];
    const float4* z = (const float4*)d_in[1];
    const float4* i = (const float4*)d_in[2];
    float4* o = (float4*)d_out;

    const int rows = in_sizes[0] / SEQ;      // B*H = 16384
    const int threads_needed = rows * 32;    // one warp per row
    const int block = 256;
    const int grid = (threads_needed + block - 1) / block;

    ifo_scan_kernel<<<grid, block>>>(f, z, i, o, rows);
}

// round 2
// speedup vs baseline: 1.0840x; 1.0840x over previous
#include <cuda_runtime.h>

// IFOPooling: h_t = f_t * h_{t-1} + i_t * z_t over seq (innermost, S=2048),
// B*H = 16384 independent rows. HBM-bound: 512MB total traffic.
//
// R2: fully-coalesced interleaved layout. Tile = 512 elems = 4 sub-tiles of
// 128. Within a sub-tile, lane l owns the 4 contiguous elements at float4
// index (tile*128 + sub*32 + l)  -> every LDG.128/STG.128 is a dense 512B
// warp request (100% sector utilization), halving L1tex wavefronts vs the
// 64B-lane-stride version. Per sub-tile: local affine map over 4 elems,
// 5-step shfl affine scan, emit. Scalar carry chains sub-tiles and tiles.
// All 12 loads of a tile are issued before the scan chain (MLP).

#define SEQ 2048

__global__ void __launch_bounds__(256) ifo_scan_kernel(
    const float4* __restrict__ f4,
    const float4* __restrict__ z4,
    const float4* __restrict__ i4,
    float4* __restrict__ o4,
    int rows)
{
    const int gwarp = (blockIdx.x * blockDim.x + threadIdx.x) >> 5;
    const int lane  = threadIdx.x & 31;
    if (gwarp >= rows) return;

    const int row4 = gwarp * (SEQ / 4);   // row offset in float4 units

    float h = 0.0f;  // carry across tiles / sub-tiles

    #pragma unroll
    for (int t = 0; t < 4; ++t) {
        const int base4 = row4 + t * 128 + lane;

        // ---- load whole tile up front (12 coalesced LDG.128) ----
        float4 fv[4], xv[4];
        #pragma unroll
        for (int j = 0; j < 4; ++j) {
            float4 ff = __ldcs(&f4[base4 + j * 32]);
            float4 zz = __ldcs(&z4[base4 + j * 32]);
            float4 ii = __ldcs(&i4[base4 + j * 32]);
            fv[j] = ff;
            xv[j] = make_float4(ii.x * zz.x, ii.y * zz.y,
                                ii.z * zz.z, ii.w * zz.w);
        }

        // ---- 4 dependent sub-tile scans ----
        #pragma unroll
        for (int j = 0; j < 4; ++j) {
            // local affine map of lane's 4 contiguous elems: h_out = A*h_in + b
            float A, b;
            b = xv[j].x;                      A = fv[j].x;
            b = fmaf(fv[j].y, b, xv[j].y);    A *= fv[j].y;
            b = fmaf(fv[j].z, b, xv[j].z);    A *= fv[j].z;
            b = fmaf(fv[j].w, b, xv[j].w);    A *= fv[j].w;

            // warp inclusive scan composing affine maps:
            // (A,b) <- (A,b) o (Ap,bp): A = A*Ap, b = A*bp + b
            #pragma unroll
            for (int d = 1; d < 32; d <<= 1) {
                float Ap = __shfl_up_sync(0xffffffffu, A, d);
                float bp = __shfl_up_sync(0xffffffffu, b, d);
                if (lane >= d) {
                    b = fmaf(A, bp, b);
                    A *= Ap;
                }
            }

            // incoming carry for this lane (exclusive prefix applied to h)
            float Aex = __shfl_up_sync(0xffffffffu, A, 1);
            float bex = __shfl_up_sync(0xffffffffu, b, 1);
            float h_in = (lane == 0) ? h : fmaf(Aex, h, bex);

            // sub-tile carry-out from lane 31's inclusive map
            float A31 = __shfl_sync(0xffffffffu, A, 31);
            float b31 = __shfl_sync(0xffffffffu, b, 31);

            // emit 4 outputs (one coalesced STG.128)
            float4 ov;
            float hh = h_in;
            hh = fmaf(fv[j].x, hh, xv[j].x); ov.x = hh;
            hh = fmaf(fv[j].y, hh, xv[j].y); ov.y = hh;
            hh = fmaf(fv[j].z, hh, xv[j].z); ov.z = hh;
            hh = fmaf(fv[j].w, hh, xv[j].w); ov.w = hh;
            __stcs(&o4[base4 + j * 32], ov);

            h = fmaf(A31, h, b31);
        }
    }
}

extern "C" void kernel_launch(void* const* d_in, const int* in_sizes, int n_in,
                              void* d_out, int out_size)
{
    const float4* f = (const float4*)d_in[0];
    const float4* z = (const float4*)d_in[1];
    const float4* i = (const float4*)d_in[2];
    float4* o = (float4*)d_out;

    const int rows = in_sizes[0] / SEQ;      // B*H = 16384
    const int threads_needed = rows * 32;    // one warp per row
    const int block = 256;
    const int grid = (threads_needed + block - 1) / block;

    ifo_scan_kernel<<<grid, block>>>(f, z, i, o, rows);
}